// round 2
// baseline (speedup 1.0000x reference)
#include <cuda_runtime.h>
#include <math.h>

// Problem constants
#define NB   8
#define CIN  16
#define HH   32
#define WW   32
#define FH   3
#define FW   3
#define OC   64
#define RDIM (FH*FW*CIN)   // 144
#define OH   30
#define OW   30
#define ROWS_PER_BLK 2

// Scratch (no allocation allowed)
__device__ float g_w[RDIM * OC];   // exp(k + 5)
__device__ float g_koff[OC];       // bias - delta_x * sum_r k
__device__ float g_dw;             // delta_w

__global__ void prep_kernel(const float* __restrict__ k,
                            const float* __restrict__ bias,
                            const float* __restrict__ dx,
                            const float* __restrict__ dw) {
    int t = threadIdx.x;
    for (int i = t; i < RDIM * OC; i += blockDim.x)
        g_w[i] = expf(k[i] + 5.0f);
    if (t < OC) {
        float s = 0.0f;
        #pragma unroll 8
        for (int r = 0; r < RDIM; r++)
            s += k[r * OC + t];
        g_koff[t] = bias[t] - dx[0] * s;
    }
    if (t == 0) g_dw = dw[0];
}

__global__ __launch_bounds__(128)
void conv_kernel(const float* __restrict__ x, float* __restrict__ out) {
    // Shared memory: 36864 + 8192 + 512 = 45568 bytes (< 48KB static limit)
    __shared__ float ws[RDIM][OC];                       // exp(k+5) weights
    __shared__ float xc[CIN][ROWS_PER_BLK + 2][WW];      // clamped x+5 slab
    __shared__ float srow[ROWS_PER_BLK + 2][WW];         // per-(row,w) channel sum of raw x

    const int n  = blockIdx.y;
    const int r0 = blockIdx.x * ROWS_PER_BLK;            // output row base == input row base
    const int t  = threadIdx.x;

    // --- Stage weights (vectorized) ---
    {
        const float4* gw4 = (const float4*)g_w;
        float4* ws4 = (float4*)&ws[0][0];
        #pragma unroll
        for (int i = 0; i < (RDIM * OC / 4) / 128; i++)   // 2304/128 = 18 iterations
            ws4[t + i * 128] = gw4[t + i * 128];
    }

    // --- Stage x slab: 4 rows x 16 C x 32 W; thread = (row, w) ---
    {
        int row  = t >> 5;     // 0..3
        int wcol = t & 31;     // 0..31
        float s = 0.0f;
        const float* xp = x + ((size_t)n * CIN * HH + (r0 + row)) * WW + wcol;
        #pragma unroll
        for (int c = 0; c < CIN; c++) {
            float v = xp[(size_t)c * HH * WW];
            s += v;                                      // raw sum (for x_sum term)
            xc[c][row][wcol] = fmaxf(v + 5.0f, 1e-12f);  // clamp(x + IN_BIAS, MIN_VAL)
        }
        srow[row][wcol] = s;
    }
    __syncthreads();

    // --- Compute: thread = (pixel in 2x30, oc half) ---
    const int pix = t & 63;
    const int ocg = t >> 6;    // 0 or 1
    if (pix < ROWS_PER_BLK * OW) {
        const int row = pix / OW;    // 0..1
        const int col = pix % OW;    // 0..29

        float acc[32];
        #pragma unroll
        for (int m = 0; m < 32; m++) acc[m] = 0.0f;

        #pragma unroll
        for (int kh = 0; kh < FH; kh++) {
            #pragma unroll
            for (int kw = 0; kw < FW; kw++) {
                #pragma unroll 4
                for (int c = 0; c < CIN; c++) {
                    const int r = (kh * FW + kw) * CIN + c;
                    const float xv = xc[c][row + kh][col + kw];
                    const float4* w4 = (const float4*)&ws[r][ocg * 32];
                    #pragma unroll
                    for (int q = 0; q < 8; q++) {
                        float4 wv = w4[q];
                        acc[q * 4 + 0] = fmaf(xv, wv.x, acc[q * 4 + 0]);
                        acc[q * 4 + 1] = fmaf(xv, wv.y, acc[q * 4 + 1]);
                        acc[q * 4 + 2] = fmaf(xv, wv.z, acc[q * 4 + 2]);
                        acc[q * 4 + 3] = fmaf(xv, wv.w, acc[q * 4 + 3]);
                    }
                }
            }
        }

        // x_sum: 3x3 window over channel-sums, times delta_w
        float xs = 0.0f;
        #pragma unroll
        for (int kh = 0; kh < 3; kh++)
            #pragma unroll
            for (int kw = 0; kw < 3; kw++)
                xs += srow[row + kh][col + kw];
        xs *= g_dw;

        const int i = r0 + row;
        float* op = out + (((size_t)n * OC + ocg * 32) * OH + i) * OW + col;
        #pragma unroll
        for (int m = 0; m < 32; m++)
            op[(size_t)m * OH * OW] = acc[m] - xs + g_koff[ocg * 32 + m];
    }
}

extern "C" void kernel_launch(void* const* d_in, const int* in_sizes, int n_in,
                              void* d_out, int out_size) {
    const float* x    = (const float*)d_in[0];
    const float* k    = (const float*)d_in[1];
    const float* bias = (const float*)d_in[2];
    const float* dx   = (const float*)d_in[3];
    const float* dw   = (const float*)d_in[4];
    float* out = (float*)d_out;

    prep_kernel<<<1, 256>>>(k, bias, dx, dw);
    dim3 grid(OH / ROWS_PER_BLK, NB);   // (15, 8)
    conv_kernel<<<grid, 128>>>(x, out);
}

// round 3
// speedup vs baseline: 1.5050x; 1.5050x over previous
#include <cuda_runtime.h>
#include <math.h>

// Problem constants
#define NB   8
#define CIN  16
#define HH   32
#define WW   32
#define OC   64
#define RDIM 144       // 3*3*16
#define OH   30
#define OW   30
#define RPB  2         // output rows per block

// Packed fp32x2 FMA (sm_100+): d = a*b + d, lanewise on 2 packed fp32
#define FMA2(d, a, b) \
    asm("fma.rn.f32x2 %0, %1, %2, %0;" : "+l"(d) : "l"(a), "l"(b))

__global__ __launch_bounds__(256, 1)
void fused_kernel(const float* __restrict__ x,
                  const float* __restrict__ k,
                  const float* __restrict__ bias,
                  const float* __restrict__ dxp,
                  const float* __restrict__ dwp,
                  float* __restrict__ out) {
    __shared__ float ws[RDIM][OC];        // exp(k+5): 36864 B
    __shared__ float xc[CIN][RPB+2][WW];  // clamped x+5 slab: 8192 B
    __shared__ float srow[RPB+2][WW];     // channel-sums of raw x: 512 B
    __shared__ float koff[OC];            // bias - dx*sum_r k: 256 B
    // total 45824 B < 48 KB static

    const int n  = blockIdx.y;
    const int r0 = blockIdx.x * RPB;
    const int t  = threadIdx.x;

    // --- Stage weights, computing exp(k+5) on the fly (fused prep) ---
    {
        const float4* g4 = (const float4*)k;
        float4* w4 = (float4*)&ws[0][0];
        #pragma unroll
        for (int i = 0; i < 9; i++) {          // 2304 float4 / 256 threads
            float4 v = g4[t + i * 256];
            v.x = expf(v.x + 5.0f);
            v.y = expf(v.y + 5.0f);
            v.z = expf(v.z + 5.0f);
            v.w = expf(v.w + 5.0f);
            w4[t + i * 256] = v;
        }
    }

    // --- Stage x slab (threads 0..127) / koff (threads 128..191) in parallel ---
    if (t < 128) {
        const int row  = t >> 5;   // 0..3
        const int wcol = t & 31;   // 0..31
        float s = 0.0f;
        const float* xp = x + ((size_t)n * CIN * HH + (r0 + row)) * WW + wcol;
        #pragma unroll
        for (int c = 0; c < CIN; c++) {
            float v = xp[(size_t)c * HH * WW];
            s += v;
            xc[c][row][wcol] = fmaxf(v + 5.0f, 1e-12f);
        }
        srow[row][wcol] = s;
    } else if (t < 192) {
        const int oc = t - 128;
        float s = 0.0f;
        #pragma unroll 8
        for (int r = 0; r < RDIM; r++)
            s += k[r * OC + oc];
        koff[oc] = bias[oc] - __ldg(dxp) * s;
    }
    __syncthreads();

    // --- Compute: thread = (pixel in 2x30, oc group of 16) ---
    const int pix = t & 63;
    const int ocg = t >> 6;        // 0..3 -> oc base = ocg*16 (warp-uniform)
    if (pix < RPB * OW) {
        const int row = pix / OW;  // 0..1
        const int col = pix % OW;  // 0..29

        unsigned long long acc[8];
        #pragma unroll
        for (int m = 0; m < 8; m++) acc[m] = 0ull;

        const float* wsbase = &ws[0][ocg * 16];

        #pragma unroll
        for (int kh = 0; kh < 3; kh++) {
            #pragma unroll
            for (int kw = 0; kw < 3; kw++) {
                #pragma unroll 4
                for (int c = 0; c < CIN; c++) {
                    const int r = (kh * 3 + kw) * CIN + c;
                    const float xv = xc[c][row + kh][col + kw];
                    unsigned long long xv2;
                    asm("mov.b64 %0, {%1, %1};" : "=l"(xv2) : "r"(__float_as_uint(xv)));
                    const ulonglong2* wp = (const ulonglong2*)(wsbase + r * OC);
                    ulonglong2 wa = wp[0];   // oc pairs 0-1, 2-3
                    ulonglong2 wb = wp[1];   // oc pairs 4-5, 6-7
                    FMA2(acc[0], xv2, wa.x);
                    FMA2(acc[1], xv2, wa.y);
                    FMA2(acc[2], xv2, wb.x);
                    FMA2(acc[3], xv2, wb.y);
                    ulonglong2 wc = wp[2];   // oc pairs 8-9, 10-11
                    ulonglong2 wd = wp[3];   // oc pairs 12-13, 14-15
                    FMA2(acc[4], xv2, wc.x);
                    FMA2(acc[5], xv2, wc.y);
                    FMA2(acc[6], xv2, wd.x);
                    FMA2(acc[7], xv2, wd.y);
                }
            }
        }

        // x_sum term: 3x3 window over channel sums, times delta_w
        float xs = 0.0f;
        #pragma unroll
        for (int kh = 0; kh < 3; kh++)
            #pragma unroll
            for (int kw = 0; kw < 3; kw++)
                xs += srow[row + kh][col + kw];
        xs *= __ldg(dwp);

        const int i = r0 + row;
        float* op = out + (((size_t)n * OC + ocg * 16) * OH + i) * OW + col;
        #pragma unroll
        for (int m = 0; m < 8; m++) {
            float lo = __uint_as_float((unsigned)(acc[m] & 0xffffffffu));
            float hi = __uint_as_float((unsigned)(acc[m] >> 32));
            op[(size_t)(2 * m)     * OH * OW] = lo - xs + koff[ocg * 16 + 2 * m];
            op[(size_t)(2 * m + 1) * OH * OW] = hi - xs + koff[ocg * 16 + 2 * m + 1];
        }
    }
}

extern "C" void kernel_launch(void* const* d_in, const int* in_sizes, int n_in,
                              void* d_out, int out_size) {
    const float* x    = (const float*)d_in[0];
    const float* k    = (const float*)d_in[1];
    const float* bias = (const float*)d_in[2];
    const float* dx   = (const float*)d_in[3];
    const float* dw   = (const float*)d_in[4];
    float* out = (float*)d_out;

    dim3 grid(OH / RPB, NB);   // (15, 8) = 120 blocks
    fused_kernel<<<grid, 256>>>(x, k, bias, dx, dw, out);
}